// round 2
// baseline (speedup 1.0000x reference)
#include <cuda_runtime.h>
#include <math.h>

#define NB     16384
#define MTOK   6
#define MPROTO 8
#define DIM    256

// ---------------- scratch (static device arrays: allowed) ----------------
__device__ float g_EL[(size_t)NB * MTOK * DIM];    // 96 MB
__device__ float g_KL[(size_t)NB * MPROTO * DIM];  // 128 MB
__device__ float g_signorm[4 * DIM];

// ---------------- kernel 0: normalize self signatures ----------------
__global__ void k_signorm(const float* __restrict__ sigs)
{
    int w = threadIdx.x >> 5, lane = threadIdx.x & 31;
    if (w < 4) {
        const float* s = sigs + w * DIM;
        float acc = 0.f;
        for (int d = lane; d < DIM; d += 32) { float v = s[d]; acc = fmaf(v, v, acc); }
        #pragma unroll
        for (int o = 16; o; o >>= 1) acc += __shfl_xor_sync(0xffffffffu, acc, o);
        float nrm = fmaxf(sqrtf(acc), 1e-12f);
        float inv = 1.0f / nrm;
        for (int d = lane; d < DIM; d += 32) g_signorm[w * DIM + d] = s[d] * inv;
    }
}

// ---------------- kernel 1: Y[r][e] = sum_d X[r][d] * L[e][d] ----------------
// 128x128 tile, BK=16, 256 threads, 8x8 register micro-tile.
__global__ void __launch_bounds__(256, 2)
k_gemm(const float* __restrict__ X, const float* __restrict__ L,
       float* __restrict__ Y)
{
    __shared__ float As[16][132];
    __shared__ float Bs[16][132];

    const int tid = threadIdx.x;
    const int tx = tid & 15, ty = tid >> 4;
    const int r0 = blockIdx.x * 128;
    const int e0 = blockIdx.y * 128;

    const int i0 = tid >> 2;          // 0..63
    const int c4 = (tid & 3) * 4;     // 0,4,8,12

    const float* a0 = X + (size_t)(r0 + i0)      * DIM + c4;
    const float* a1 = X + (size_t)(r0 + i0 + 64) * DIM + c4;
    const float* b0 = L + (size_t)(e0 + i0)      * DIM + c4;
    const float* b1 = L + (size_t)(e0 + i0 + 64) * DIM + c4;

    float acc[8][8] = {};

    for (int k0 = 0; k0 < DIM; k0 += 16) {
        float4 av0 = *(const float4*)(a0 + k0);
        float4 av1 = *(const float4*)(a1 + k0);
        float4 bv0 = *(const float4*)(b0 + k0);
        float4 bv1 = *(const float4*)(b1 + k0);
        __syncthreads();   // previous tile fully consumed
        As[c4 + 0][i0] = av0.x; As[c4 + 1][i0] = av0.y;
        As[c4 + 2][i0] = av0.z; As[c4 + 3][i0] = av0.w;
        As[c4 + 0][i0 + 64] = av1.x; As[c4 + 1][i0 + 64] = av1.y;
        As[c4 + 2][i0 + 64] = av1.z; As[c4 + 3][i0 + 64] = av1.w;
        Bs[c4 + 0][i0] = bv0.x; Bs[c4 + 1][i0] = bv0.y;
        Bs[c4 + 2][i0] = bv0.z; Bs[c4 + 3][i0] = bv0.w;
        Bs[c4 + 0][i0 + 64] = bv1.x; Bs[c4 + 1][i0 + 64] = bv1.y;
        Bs[c4 + 2][i0 + 64] = bv1.z; Bs[c4 + 3][i0 + 64] = bv1.w;
        __syncthreads();

        #pragma unroll
        for (int kk = 0; kk < 16; kk++) {
            float4 af0 = *(const float4*)&As[kk][ty * 8];
            float4 af1 = *(const float4*)&As[kk][ty * 8 + 4];
            float4 bf0 = *(const float4*)&Bs[kk][tx * 8];
            float4 bf1 = *(const float4*)&Bs[kk][tx * 8 + 4];
            float a[8] = {af0.x, af0.y, af0.z, af0.w, af1.x, af1.y, af1.z, af1.w};
            float b[8] = {bf0.x, bf0.y, bf0.z, bf0.w, bf1.x, bf1.y, bf1.z, bf1.w};
            #pragma unroll
            for (int i = 0; i < 8; i++)
                #pragma unroll
                for (int j = 0; j < 8; j++)
                    acc[i][j] = fmaf(a[i], b[j], acc[i][j]);
        }
    }

    #pragma unroll
    for (int i = 0; i < 8; i++) {
        float4 v0 = make_float4(acc[i][0], acc[i][1], acc[i][2], acc[i][3]);
        float4 v1 = make_float4(acc[i][4], acc[i][5], acc[i][6], acc[i][7]);
        float* dst = Y + (size_t)(r0 + ty * 8 + i) * DIM + e0 + tx * 8;
        *(float4*)dst       = v0;
        *(float4*)(dst + 4) = v1;
    }
}

// ---------------- kernel 2: per-batch epilogue ----------------
__global__ void __launch_bounds__(256)
k_epilogue(const float* __restrict__ E, const float* __restrict__ Kp,
           const float* __restrict__ danger, const float* __restrict__ w_prev,
           const float* __restrict__ fitness, const float* __restrict__ crisis,
           const float* __restrict__ proto_conf,
           float* __restrict__ out_w, float* __restrict__ out_P)
{
    const int b   = blockIdx.x;
    const int tid = threadIdx.x;
    const int w   = tid >> 5, lane = tid & 31;

    __shared__ float sEL[6][256];
    __shared__ float sKL[8][256];
    __shared__ float sE [6][256];
    __shared__ float sK [8][256];
    __shared__ float sD [256];
    __shared__ float sCross[48];
    __shared__ float sC[48];
    __shared__ float sP[48];
    __shared__ float s_nE[6], s_co[6], s_tp[6];
    __shared__ float s_nK[8], s_pss[8];

    // loads (all coalesced float4)
    {
        const float4* p;
        p = (const float4*)(g_EL + (size_t)b * 6 * 256);
        for (int i = tid; i < 384; i += 256) ((float4*)sEL)[i] = p[i];
        p = (const float4*)(g_KL + (size_t)b * 8 * 256);
        for (int i = tid; i < 512; i += 256) ((float4*)sKL)[i] = p[i];
        p = (const float4*)(E + (size_t)b * 6 * 256);
        for (int i = tid; i < 384; i += 256) ((float4*)sE)[i] = p[i];
        p = (const float4*)(Kp + (size_t)b * 8 * 256);
        for (int i = tid; i < 512; i += 256) ((float4*)sK)[i] = p[i];
        if (tid < 64) ((float4*)sD)[tid] = ((const float4*)(danger + (size_t)b * 256))[tid];
    }
    __syncthreads();

    // ---- K-side stats: warp w handles proto n=w ----
    {
        const int n = w;
        float nk = 0.f, kk2 = 0.f, d0 = 0.f, d1 = 0.f, d2 = 0.f, d3 = 0.f;
        for (int dd = lane; dd < 256; dd += 32) {
            float kl = sKL[n][dd];
            nk = fmaf(kl, kl, nk);
            float kv = sK[n][dd];
            kk2 = fmaf(kv, kv, kk2);
            d0 = fmaf(kv, g_signorm[0 * 256 + dd], d0);
            d1 = fmaf(kv, g_signorm[1 * 256 + dd], d1);
            d2 = fmaf(kv, g_signorm[2 * 256 + dd], d2);
            d3 = fmaf(kv, g_signorm[3 * 256 + dd], d3);
        }
        #pragma unroll
        for (int o = 16; o; o >>= 1) {
            nk  += __shfl_xor_sync(~0u, nk,  o);
            kk2 += __shfl_xor_sync(~0u, kk2, o);
            d0  += __shfl_xor_sync(~0u, d0,  o);
            d1  += __shfl_xor_sync(~0u, d1,  o);
            d2  += __shfl_xor_sync(~0u, d2,  o);
            d3  += __shfl_xor_sync(~0u, d3,  o);
        }
        if (lane == 0) {
            s_nK[n] = nk;
            float kn = fmaxf(sqrtf(kk2), 1e-12f);
            float mx = fmaxf(fmaxf(d0, d1), fmaxf(d2, d3));
            s_pss[n] = mx / kn;
        }
        // cross dots: EL[m] . KL[n]
        #pragma unroll
        for (int m = 0; m < 6; m++) {
            float cx = 0.f;
            for (int dd = lane; dd < 256; dd += 32)
                cx = fmaf(sEL[m][dd], sKL[n][dd], cx);
            #pragma unroll
            for (int o = 16; o; o >>= 1) cx += __shfl_xor_sync(~0u, cx, o);
            if (lane == 0) sCross[m * 8 + n] = cx;
        }
    }

    // ---- E-side stats: warps 0..5 handle token m=w ----
    if (w < 6) {
        const int m = w;
        float ne = 0.f, ee = 0.f, co = 0.f, e0 = 0.f, e1 = 0.f, e2 = 0.f, e3 = 0.f;
        for (int dd = lane; dd < 256; dd += 32) {
            float el = sEL[m][dd];
            ne = fmaf(el, el, ne);
            float ev = sE[m][dd];
            ee = fmaf(ev, ev, ee);
            co = fmaf(ev, sD[dd], co);
            e0 = fmaf(ev, g_signorm[0 * 256 + dd], e0);
            e1 = fmaf(ev, g_signorm[1 * 256 + dd], e1);
            e2 = fmaf(ev, g_signorm[2 * 256 + dd], e2);
            e3 = fmaf(ev, g_signorm[3 * 256 + dd], e3);
        }
        #pragma unroll
        for (int o = 16; o; o >>= 1) {
            ne += __shfl_xor_sync(~0u, ne, o);
            ee += __shfl_xor_sync(~0u, ee, o);
            co += __shfl_xor_sync(~0u, co, o);
            e0 += __shfl_xor_sync(~0u, e0, o);
            e1 += __shfl_xor_sync(~0u, e1, o);
            e2 += __shfl_xor_sync(~0u, e2, o);
            e3 += __shfl_xor_sync(~0u, e3, o);
        }
        if (lane == 0) {
            s_nE[m] = ne;
            s_co[m] = co;
            float en = fmaxf(sqrtf(ee), 1e-12f);
            float worst = fmaxf(fmaxf(e0, e1), fmaxf(e2, e3)) / en;
            s_tp[m] = fmaxf(1.0f * worst - 0.1f, 0.0f);   // relu(KAPPA*worst - EPS_TOL)
        }
    }
    __syncthreads();

    // ---- build cost matrix C[6][8] ----
    if (tid < 48) {
        const int m = tid / 8, n = tid & 7;
        float msq  = s_nE[m] + s_nK[n] - 2.0f * sCross[tid];
        float dist = sqrtf(fmaxf(msq, 1e-8f));
        float c = dist - 0.5f * s_co[m] + 2.0f * s_tp[m]
                + 0.3f * proto_conf[(size_t)b * 8 + n];
        sC[tid] = c;
    }
    __syncthreads();

    // ---- Sinkhorn (warp 0, width-8 lane groups; always 10 iterations:
    //      the reference's early-stop is a GLOBAL max over all batches and
    //      with eps=0.05 never triggers within 10 iters) ----
    if (w == 0) {
        const int n = lane & 7;
        const float INV_EPS = 1.0f / (0.05f + 1e-8f);
        const float LOG_U = logf(1.0f / 6.0f + 1e-8f);
        const float LOG_V = logf(0.125f     + 1e-8f);
        float lk[6], la[6], lb = 0.0f;
        #pragma unroll
        for (int m = 0; m < 6; m++) { lk[m] = -sC[m * 8 + n] * INV_EPS; la[m] = 0.f; }

        for (int it = 0; it < 10; it++) {
            float t2[6];
            #pragma unroll
            for (int m = 0; m < 6; m++) {
                float t = lk[m] + lb;
                float r = t;
                r = fmaxf(r, __shfl_xor_sync(~0u, r, 1, 8));
                r = fmaxf(r, __shfl_xor_sync(~0u, r, 2, 8));
                r = fmaxf(r, __shfl_xor_sync(~0u, r, 4, 8));
                float s = expf(t - r);
                s += __shfl_xor_sync(~0u, s, 1, 8);
                s += __shfl_xor_sync(~0u, s, 2, 8);
                s += __shfl_xor_sync(~0u, s, 4, 8);
                la[m] = LOG_U - (r + logf(s));          // na
                t2[m] = lk[m] + la[m];
            }
            float cm = t2[0];
            #pragma unroll
            for (int m = 1; m < 6; m++) cm = fmaxf(cm, t2[m]);
            float cs = 0.f;
            #pragma unroll
            for (int m = 0; m < 6; m++) cs += expf(t2[m] - cm);
            lb = LOG_V - (cm + logf(cs));               // nb
        }

        float pm = 0.0f;
        #pragma unroll
        for (int m = 0; m < 6; m++) {
            float p = expf(la[m] + lk[m] + lb);
            p = fminf(fmaxf(p, 0.0f), 1.0f);
            if (lane < 8) sP[m * 8 + n] = p;
            pm += p;
        }

        // ---- replicator (same lanes; pm held in-register) ----
        float wp  = w_prev [(size_t)b * 8 + n];
        float fit = fitness[(size_t)b * 8 + n];
        float bl = wp * fit;
        bl += __shfl_xor_sync(~0u, bl, 1, 8);
        bl += __shfl_xor_sync(~0u, bl, 2, 8);
        bl += __shfl_xor_sync(~0u, bl, 4, 8);
        float eta = 0.05f + 0.1f * crisis[b];
        float lt = logf(wp + 1e-8f) + eta * (fit - bl) - 0.5f * s_pss[n];
        float mx = lt;
        mx = fmaxf(mx, __shfl_xor_sync(~0u, mx, 1, 8));
        mx = fmaxf(mx, __shfl_xor_sync(~0u, mx, 2, 8));
        mx = fmaxf(mx, __shfl_xor_sync(~0u, mx, 4, 8));
        float ex = expf(lt - mx);
        float ss = ex;
        ss += __shfl_xor_sync(~0u, ss, 1, 8);
        ss += __shfl_xor_sync(~0u, ss, 2, 8);
        ss += __shfl_xor_sync(~0u, ss, 4, 8);
        float tilde = ex / ss;
        float wv = 0.7f * tilde + 0.3f * pm;
        float ws = wv;
        ws += __shfl_xor_sync(~0u, ws, 1, 8);
        ws += __shfl_xor_sync(~0u, ws, 2, 8);
        ws += __shfl_xor_sync(~0u, ws, 4, 8);
        wv = wv / (ws + 1e-8f);
        wv = fminf(fmaxf(wv, 1e-6f), 1.0f);
        if (lane < 8) out_w[(size_t)b * 8 + n] = wv;
    }
    __syncthreads();

    if (tid < 48) out_P[(size_t)b * 48 + tid] = sP[tid];
}

// ---------------- launch ----------------
extern "C" void kernel_launch(void* const* d_in, const int* in_sizes, int n_in,
                              void* d_out, int out_size)
{
    const float* E          = (const float*)d_in[0];
    const float* K          = (const float*)d_in[1];
    const float* danger     = (const float*)d_in[2];
    const float* w_prev     = (const float*)d_in[3];
    const float* fitness    = (const float*)d_in[4];
    const float* crisis     = (const float*)d_in[5];
    const float* proto_conf = (const float*)d_in[6];
    const float* metric_L   = (const float*)d_in[7];
    const float* self_sigs  = (const float*)d_in[8];

    float* out   = (float*)d_out;
    float* out_w = out;                       // [B, 8]
    float* out_P = out + (size_t)NB * 8;      // [B, 6, 8]

    void* pEL = nullptr;
    void* pKL = nullptr;
    cudaGetSymbolAddress(&pEL, g_EL);
    cudaGetSymbolAddress(&pKL, g_KL);

    k_signorm<<<1, 128>>>(self_sigs);
    k_gemm<<<dim3(NB * MTOK   / 128, 2), 256>>>(E, metric_L, (float*)pEL);
    k_gemm<<<dim3(NB * MPROTO / 128, 2), 256>>>(K, metric_L, (float*)pKL);
    k_epilogue<<<NB, 256>>>(E, K, danger, w_prev, fitness, crisis, proto_conf,
                            out_w, out_P);
}

// round 5
// speedup vs baseline: 1.2198x; 1.2198x over previous
#include <cuda_runtime.h>
#include <cuda_bf16.h>
#include <cstdint>
#include <math.h>

#define NB     16384
#define MTOK   6
#define MPROTO 8
#define DIM    256

// ---------------- scratch (static device arrays: allowed) ----------------
__device__ float g_EL[(size_t)NB * MTOK * DIM];    // 96 MB
__device__ float g_KL[(size_t)NB * MPROTO * DIM];  // 128 MB
__device__ float g_signorm[4 * DIM];
// Pre-converted, pre-swizzled L operand: 4 k-chunks of [256 e-rows x 64 k] bf16
__device__ __nv_bfloat16 g_Lh[4 * 256 * 64];
__device__ __nv_bfloat16 g_Ll[4 * 256 * 64];

// ---------------- helpers ----------------
__device__ __forceinline__ uint32_t smem_u32(const void* p) {
    uint32_t a;
    asm("{ .reg .u64 t; cvta.to.shared.u64 t, %1; cvt.u32.u64 %0, t; }" : "=r"(a) : "l"(p));
    return a;
}
#define SWZ128(off) ((off) ^ (((off) >> 3) & 0x70))

#define LDSM4(r, addr)                                                          \
    asm volatile("ldmatrix.sync.aligned.m8n8.x4.shared.b16 {%0,%1,%2,%3}, [%4];"\
        : "=r"((r)[0]), "=r"((r)[1]), "=r"((r)[2]), "=r"((r)[3]) : "r"(addr))

#define MMA_BF16(d, a, b)                                                       \
    asm volatile("mma.sync.aligned.m16n8k16.row.col.f32.bf16.bf16.f32 "         \
        "{%0,%1,%2,%3}, {%4,%5,%6,%7}, {%8,%9}, {%0,%1,%2,%3};"                 \
        : "+f"((d)[0]), "+f"((d)[1]), "+f"((d)[2]), "+f"((d)[3])                \
        : "r"((a)[0]), "r"((a)[1]), "r"((a)[2]), "r"((a)[3]),                   \
          "r"((b)[0]), "r"((b)[1]))

#define CP16(dst, src)                                                          \
    asm volatile("cp.async.cg.shared.global [%0], [%1], 16;"                    \
        :: "r"(dst), "l"(src) : "memory")
#define CP_COMMIT() asm volatile("cp.async.commit_group;" ::: "memory")
#define CP_WAIT0()  asm volatile("cp.async.wait_group 0;" ::: "memory")

// ---------------- kernel 0: normalize self signatures ----------------
__global__ void k_signorm(const float* __restrict__ sigs)
{
    int w = threadIdx.x >> 5, lane = threadIdx.x & 31;
    if (w < 4) {
        const float* s = sigs + w * DIM;
        float acc = 0.f;
        for (int d = lane; d < DIM; d += 32) { float v = s[d]; acc = fmaf(v, v, acc); }
        #pragma unroll
        for (int o = 16; o; o >>= 1) acc += __shfl_xor_sync(0xffffffffu, acc, o);
        float inv = 1.0f / fmaxf(sqrtf(acc), 1e-12f);
        for (int d = lane; d < DIM; d += 32) g_signorm[w * DIM + d] = s[d] * inv;
    }
}

// ---------------- kernel 0b: convert+pre-swizzle L into bf16 hi/lo ----------------
// chunk c holds e-rows 0..255 x k-cols [c*64 .. c*64+63], SW128 within 128B rows.
__global__ void k_prepL(const float* __restrict__ L)
{
    int r = threadIdx.x;           // e-row, 0..255
    for (int k = 0; k < 256; k++) {
        float x = L[r * 256 + k];
        __nv_bfloat16 h = __float2bfloat16(x);
        __nv_bfloat16 l = __float2bfloat16(x - __bfloat162float(h));
        int c  = k >> 6;
        int kc = k & 63;
        uint32_t off = SWZ128((uint32_t)(r * 128 + kc * 2));
        g_Lh[c * 16384 + (off >> 1)] = h;
        g_Ll[c * 16384 + (off >> 1)] = l;
    }
}

// ---------------- kernel 1: mma.sync GEMM  Y = X * L^T  (bf16x3 split) ----------------
// grid = (rows/128, 2). Block: 128 rows x 128 e-cols. 8 warps as (4 m) x (2 n):
// warp tile 32x64. K in four 64-wide chunks; A double-buffered, B fully resident.
// Dyn smem: [Abuf0: Ah 16K | Al 16K][Abuf1: 32K][B: 4 chunks x (Bh 16K | Bl 16K) = 128K]
#define A_BUF   32768
#define B_BASE  65536
#define SMEM_TOT (B_BASE + 131072)

__global__ void __launch_bounds__(256, 1)
k_gemm_mma(const float* __restrict__ X, float* __restrict__ Y)
{
    extern __shared__ char dsm[];
    const int tid  = threadIdx.x;
    const int w    = tid >> 5, lane = tid & 31;
    const int row0 = blockIdx.x * 128;
    const int e0   = blockIdx.y * 128;
    const uint32_t smb = smem_u32(dsm);

    // ---- B: cp.async the whole 128KB (this block's e-half, all 4 k-chunks)
    {
        const char* srcH = (const char*)g_Lh + blockIdx.y * 16384;
        const char* srcL = (const char*)g_Ll + blockIdx.y * 16384;
        #pragma unroll
        for (int c = 0; c < 4; c++) {
            uint32_t dH = smb + B_BASE + c * 32768;
            uint32_t dL = dH + 16384;
            for (int i = tid; i < 1024; i += 256) {
                CP16(dH + i * 16, srcH + c * 32768 + i * 16);
                CP16(dL + i * 16, srcL + c * 32768 + i * 16);
            }
        }
        CP_COMMIT();
    }

    // ---- A load/convert mapping: thread t -> row t>>1, col half (t&1)*32
    const int arow  = tid >> 1;
    const int acol0 = (tid & 1) * 32;
    float4 pref[8];

    // prologue: load chunk 0
    {
        const float4* src = (const float4*)(X + (size_t)(row0 + arow) * DIM + acol0);
        #pragma unroll
        for (int q = 0; q < 8; q++) pref[q] = src[q];
    }
    CP_WAIT0();

    // store chunk 0 into buf 0
    {
        char* base = dsm;
        #pragma unroll
        for (int q = 0; q < 8; q++) {
            float4 v = pref[q];
            int colb = acol0 + q * 4;
            __nv_bfloat16 h0 = __float2bfloat16(v.x);
            __nv_bfloat16 h1 = __float2bfloat16(v.y);
            __nv_bfloat16 h2 = __float2bfloat16(v.z);
            __nv_bfloat16 h3 = __float2bfloat16(v.w);
            __nv_bfloat16 l0 = __float2bfloat16(v.x - __bfloat162float(h0));
            __nv_bfloat16 l1 = __float2bfloat16(v.y - __bfloat162float(h1));
            __nv_bfloat16 l2 = __float2bfloat16(v.z - __bfloat162float(h2));
            __nv_bfloat16 l3 = __float2bfloat16(v.w - __bfloat162float(h3));
            uint32_t off = SWZ128((uint32_t)(arow * 128 + colb * 2));
            __nv_bfloat162 hA; hA.x = h0; hA.y = h1;
            __nv_bfloat162 hB; hB.x = h2; hB.y = h3;
            __nv_bfloat162 lA; lA.x = l0; lA.y = l1;
            __nv_bfloat162 lB; lB.x = l2; lB.y = l3;
            *(__nv_bfloat162*)(base + off)             = hA;
            *(__nv_bfloat162*)(base + off + 4)         = hB;
            *(__nv_bfloat162*)(base + 16384 + off)     = lA;
            *(__nv_bfloat162*)(base + 16384 + off + 4) = lB;
        }
    }
    __syncthreads();

    // ---- warp coords + accumulators
    const int mbase = (w & 3) * 32;
    const int nbase = (w >> 2) * 64;
    float acc[2][8][4];
    #pragma unroll
    for (int mt = 0; mt < 2; mt++)
        #pragma unroll
        for (int nt = 0; nt < 8; nt++)
            #pragma unroll
            for (int q = 0; q < 4; q++) acc[mt][nt][q] = 0.0f;

    #pragma unroll
    for (int c = 0; c < 4; c++) {
        // prefetch next A chunk (LDGs overlap the MMA work below)
        if (c < 3) {
            const float4* src = (const float4*)(X + (size_t)(row0 + arow) * DIM
                                                + (c + 1) * 64 + acol0);
            #pragma unroll
            for (int q = 0; q < 8; q++) pref[q] = src[q];
        }

        // compute on A buf (c&1), B chunk c
        {
            const uint32_t aH = smb + (c & 1) * A_BUF;
            const uint32_t aL = aH + 16384;
            const uint32_t bH = smb + B_BASE + c * 32768;
            const uint32_t bL = bH + 16384;
            const int arw = mbase + (lane & 15);
            const int nrw = nbase + (lane & 7) + ((lane >> 4) << 3);

            #pragma unroll
            for (int ks = 0; ks < 4; ks++) {
                uint32_t ah[2][4], al[2][4], bh[4][4], bl[4][4];
                const int akc = ks * 16 + (lane >> 4) * 8;
                const int bkc = ks * 16 + ((lane >> 3) & 1) * 8;
                #pragma unroll
                for (int mt = 0; mt < 2; mt++) {
                    uint32_t off = SWZ128((uint32_t)((arw + mt * 16) * 128 + akc * 2));
                    LDSM4(ah[mt], aH + off);
                    LDSM4(al[mt], aL + off);
                }
                #pragma unroll
                for (int g = 0; g < 4; g++) {
                    uint32_t off = SWZ128((uint32_t)((nrw + g * 16) * 128 + bkc * 2));
                    LDSM4(bh[g], bH + off);
                    LDSM4(bl[g], bL + off);
                }
                #pragma unroll
                for (int mt = 0; mt < 2; mt++)
                    #pragma unroll
                    for (int nt = 0; nt < 8; nt++) {
                        uint32_t* Bh = &bh[nt >> 1][(nt & 1) * 2];
                        uint32_t* Bl = &bl[nt >> 1][(nt & 1) * 2];
                        MMA_BF16(acc[mt][nt], ah[mt], Bh);
                        MMA_BF16(acc[mt][nt], ah[mt], Bl);
                        MMA_BF16(acc[mt][nt], al[mt], Bh);
                    }
            }
        }
        __syncthreads();

        // store prefetched A into the other buffer
        if (c < 3) {
            char* base = dsm + ((c + 1) & 1) * A_BUF;
            #pragma unroll
            for (int q = 0; q < 8; q++) {
                float4 v = pref[q];
                int colb = acol0 + q * 4;
                __nv_bfloat16 h0 = __float2bfloat16(v.x);
                __nv_bfloat16 h1 = __float2bfloat16(v.y);
                __nv_bfloat16 h2 = __float2bfloat16(v.z);
                __nv_bfloat16 h3 = __float2bfloat16(v.w);
                __nv_bfloat16 l0 = __float2bfloat16(v.x - __bfloat162float(h0));
                __nv_bfloat16 l1 = __float2bfloat16(v.y - __bfloat162float(h1));
                __nv_bfloat16 l2 = __float2bfloat16(v.z - __bfloat162float(h2));
                __nv_bfloat16 l3 = __float2bfloat16(v.w - __bfloat162float(h3));
                uint32_t off = SWZ128((uint32_t)(arow * 128 + colb * 2));
                __nv_bfloat162 hA; hA.x = h0; hA.y = h1;
                __nv_bfloat162 hB; hB.x = h2; hB.y = h3;
                __nv_bfloat162 lA; lA.x = l0; lA.y = l1;
                __nv_bfloat162 lB; lB.x = l2; lB.y = l3;
                *(__nv_bfloat162*)(base + off)             = hA;
                *(__nv_bfloat162*)(base + off + 4)         = hB;
                *(__nv_bfloat162*)(base + 16384 + off)     = lA;
                *(__nv_bfloat162*)(base + 16384 + off + 4) = lB;
            }
            __syncthreads();
        }
    }

    // ---- store accumulators (float2, coalesced in 32B groups per 4 lanes)
    #pragma unroll
    for (int mt = 0; mt < 2; mt++) {
        const int row = row0 + mbase + mt * 16 + (lane >> 2);
        #pragma unroll
        for (int nt = 0; nt < 8; nt++) {
            const int col = e0 + nbase + nt * 8 + (lane & 3) * 2;
            float2 v0 = make_float2(acc[mt][nt][0], acc[mt][nt][1]);
            float2 v1 = make_float2(acc[mt][nt][2], acc[mt][nt][3]);
            *(float2*)(Y + (size_t)row * DIM + col)       = v0;
            *(float2*)(Y + (size_t)(row + 8) * DIM + col) = v1;
        }
    }
}

// ---------------- kernel 2: per-batch epilogue (unchanged, known-good) ----------------
__global__ void __launch_bounds__(256)
k_epilogue(const float* __restrict__ E, const float* __restrict__ Kp,
           const float* __restrict__ danger, const float* __restrict__ w_prev,
           const float* __restrict__ fitness, const float* __restrict__ crisis,
           const float* __restrict__ proto_conf,
           float* __restrict__ out_w, float* __restrict__ out_P)
{
    const int b   = blockIdx.x;
    const int tid = threadIdx.x;
    const int w   = tid >> 5, lane = tid & 31;

    __shared__ float sEL[6][256];
    __shared__ float sKL[8][256];
    __shared__ float sE [6][256];
    __shared__ float sK [8][256];
    __shared__ float sD [256];
    __shared__ float sCross[48];
    __shared__ float sC[48];
    __shared__ float sP[48];
    __shared__ float s_nE[6], s_co[6], s_tp[6];
    __shared__ float s_nK[8], s_pss[8];

    {
        const float4* p;
        p = (const float4*)(g_EL + (size_t)b * 6 * 256);
        for (int i = tid; i < 384; i += 256) ((float4*)sEL)[i] = p[i];
        p = (const float4*)(g_KL + (size_t)b * 8 * 256);
        for (int i = tid; i < 512; i += 256) ((float4*)sKL)[i] = p[i];
        p = (const float4*)(E + (size_t)b * 6 * 256);
        for (int i = tid; i < 384; i += 256) ((float4*)sE)[i] = p[i];
        p = (const float4*)(Kp + (size_t)b * 8 * 256);
        for (int i = tid; i < 512; i += 256) ((float4*)sK)[i] = p[i];
        if (tid < 64) ((float4*)sD)[tid] = ((const float4*)(danger + (size_t)b * 256))[tid];
    }
    __syncthreads();

    {
        const int n = w;
        float nk = 0.f, kk2 = 0.f, d0 = 0.f, d1 = 0.f, d2 = 0.f, d3 = 0.f;
        for (int dd = lane; dd < 256; dd += 32) {
            float kl = sKL[n][dd];
            nk = fmaf(kl, kl, nk);
            float kv = sK[n][dd];
            kk2 = fmaf(kv, kv, kk2);
            d0 = fmaf(kv, g_signorm[0 * 256 + dd], d0);
            d1 = fmaf(kv, g_signorm[1 * 256 + dd], d1);
            d2 = fmaf(kv, g_signorm[2 * 256 + dd], d2);
            d3 = fmaf(kv, g_signorm[3 * 256 + dd], d3);
        }
        #pragma unroll
        for (int o = 16; o; o >>= 1) {
            nk  += __shfl_xor_sync(~0u, nk,  o);
            kk2 += __shfl_xor_sync(~0u, kk2, o);
            d0  += __shfl_xor_sync(~0u, d0,  o);
            d1  += __shfl_xor_sync(~0u, d1,  o);
            d2  += __shfl_xor_sync(~0u, d2,  o);
            d3  += __shfl_xor_sync(~0u, d3,  o);
        }
        if (lane == 0) {
            s_nK[n] = nk;
            float kn = fmaxf(sqrtf(kk2), 1e-12f);
            float mx = fmaxf(fmaxf(d0, d1), fmaxf(d2, d3));
            s_pss[n] = mx / kn;
        }
        #pragma unroll
        for (int m = 0; m < 6; m++) {
            float cx = 0.f;
            for (int dd = lane; dd < 256; dd += 32)
                cx = fmaf(sEL[m][dd], sKL[n][dd], cx);
            #pragma unroll
            for (int o = 16; o; o >>= 1) cx += __shfl_xor_sync(~0u, cx, o);
            if (lane == 0) sCross[m * 8 + n] = cx;
        }
    }

    if (w < 6) {
        const int m = w;
        float ne = 0.f, ee = 0.f, co = 0.f, e0 = 0.f, e1 = 0.f, e2 = 0.f, e3 = 0.f;
        for (int dd = lane; dd < 256; dd += 32) {
            float el = sEL[m][dd];
            ne = fmaf(el, el, ne);
            float ev = sE[m][dd];
            ee = fmaf(ev, ev, ee);
            co = fmaf(ev, sD[dd], co);
            e0 = fmaf(ev, g_signorm[0 * 256 + dd], e0);
            e1 = fmaf(ev, g_signorm[1 * 256 + dd], e1);
            e2 = fmaf(ev, g_signorm[2 * 256 + dd], e2);
            e3 = fmaf(ev, g_signorm[3 * 256 + dd], e3);
        }
        #pragma unroll
        for (int o = 16; o; o >>= 1) {
            ne += __shfl_xor_sync(~0u, ne, o);
            ee += __shfl_xor_sync(~0u, ee, o);
            co += __shfl_xor_sync(~0u, co, o);
            e0 += __shfl_xor_sync(~0u, e0, o);
            e1 += __shfl_xor_sync(~0u, e1, o);
            e2 += __shfl_xor_sync(~0u, e2, o);
            e3 += __shfl_xor_sync(~0u, e3, o);
        }
        if (lane == 0) {
            s_nE[m] = ne;
            s_co[m] = co;
            float en = fmaxf(sqrtf(ee), 1e-12f);
            float worst = fmaxf(fmaxf(e0, e1), fmaxf(e2, e3)) / en;
            s_tp[m] = fmaxf(1.0f * worst - 0.1f, 0.0f);
        }
    }
    __syncthreads();

    if (tid < 48) {
        const int m = tid / 8, n = tid & 7;
        float msq  = s_nE[m] + s_nK[n] - 2.0f * sCross[tid];
        float dist = sqrtf(fmaxf(msq, 1e-8f));
        float c = dist - 0.5f * s_co[m] + 2.0f * s_tp[m]
                + 0.3f * proto_conf[(size_t)b * 8 + n];
        sC[tid] = c;
    }
    __syncthreads();

    if (w == 0) {
        const int n = lane & 7;
        const float INV_EPS = 1.0f / (0.05f + 1e-8f);
        const float LOG_U = logf(1.0f / 6.0f + 1e-8f);
        const float LOG_V = logf(0.125f     + 1e-8f);
        float lk[6], la[6], lb = 0.0f;
        #pragma unroll
        for (int m = 0; m < 6; m++) { lk[m] = -sC[m * 8 + n] * INV_EPS; la[m] = 0.f; }

        for (int it = 0; it < 10; it++) {
            float t2[6];
            #pragma unroll
            for (int m = 0; m < 6; m++) {
                float t = lk[m] + lb;
                float r = t;
                r = fmaxf(r, __shfl_xor_sync(~0u, r, 1, 8));
                r = fmaxf(r, __shfl_xor_sync(~0u, r, 2, 8));
                r = fmaxf(r, __shfl_xor_sync(~0u, r, 4, 8));
                float s = expf(t - r);
                s += __shfl_xor_sync(~0u, s, 1, 8);
                s += __shfl_xor_sync(~0u, s, 2, 8);
                s += __shfl_xor_sync(~0u, s, 4, 8);
                la[m] = LOG_U - (r + logf(s));
                t2[m] = lk[m] + la[m];
            }
            float cm = t2[0];
            #pragma unroll
            for (int m = 1; m < 6; m++) cm = fmaxf(cm, t2[m]);
            float cs = 0.f;
            #pragma unroll
            for (int m = 0; m < 6; m++) cs += expf(t2[m] - cm);
            lb = LOG_V - (cm + logf(cs));
        }

        float pm = 0.0f;
        #pragma unroll
        for (int m = 0; m < 6; m++) {
            float p = expf(la[m] + lk[m] + lb);
            p = fminf(fmaxf(p, 0.0f), 1.0f);
            if (lane < 8) sP[m * 8 + n] = p;
            pm += p;
        }

        float wp  = w_prev [(size_t)b * 8 + n];
        float fit = fitness[(size_t)b * 8 + n];
        float bl = wp * fit;
        bl += __shfl_xor_sync(~0u, bl, 1, 8);
        bl += __shfl_xor_sync(~0u, bl, 2, 8);
        bl += __shfl_xor_sync(~0u, bl, 4, 8);
        float eta = 0.05f + 0.1f * crisis[b];
        float lt = logf(wp + 1e-8f) + eta * (fit - bl) - 0.5f * s_pss[n];
        float mx = lt;
        mx = fmaxf(mx, __shfl_xor_sync(~0u, mx, 1, 8));
        mx = fmaxf(mx, __shfl_xor_sync(~0u, mx, 2, 8));
        mx = fmaxf(mx, __shfl_xor_sync(~0u, mx, 4, 8));
        float ex = expf(lt - mx);
        float ss = ex;
        ss += __shfl_xor_sync(~0u, ss, 1, 8);
        ss += __shfl_xor_sync(~0u, ss, 2, 8);
        ss += __shfl_xor_sync(~0u, ss, 4, 8);
        float tilde = ex / ss;
        float wv = 0.7f * tilde + 0.3f * pm;
        float ws = wv;
        ws += __shfl_xor_sync(~0u, ws, 1, 8);
        ws += __shfl_xor_sync(~0u, ws, 2, 8);
        ws += __shfl_xor_sync(~0u, ws, 4, 8);
        wv = wv / (ws + 1e-8f);
        wv = fminf(fmaxf(wv, 1e-6f), 1.0f);
        if (lane < 8) out_w[(size_t)b * 8 + n] = wv;
    }
    __syncthreads();

    if (tid < 48) out_P[(size_t)b * 48 + tid] = sP[tid];
}

// ---------------- launch ----------------
extern "C" void kernel_launch(void* const* d_in, const int* in_sizes, int n_in,
                              void* d_out, int out_size)
{
    const float* E          = (const float*)d_in[0];
    const float* K          = (const float*)d_in[1];
    const float* danger     = (const float*)d_in[2];
    const float* w_prev     = (const float*)d_in[3];
    const float* fitness    = (const float*)d_in[4];
    const float* crisis     = (const float*)d_in[5];
    const float* proto_conf = (const float*)d_in[6];
    const float* metric_L   = (const float*)d_in[7];
    const float* self_sigs  = (const float*)d_in[8];

    float* out   = (float*)d_out;
    float* out_w = out;                       // [B, 8]
    float* out_P = out + (size_t)NB * 8;      // [B, 6, 8]

    void* pEL = nullptr;
    void* pKL = nullptr;
    cudaGetSymbolAddress(&pEL, g_EL);
    cudaGetSymbolAddress(&pKL, g_KL);

    cudaFuncSetAttribute(k_gemm_mma, cudaFuncAttributeMaxDynamicSharedMemorySize,
                         SMEM_TOT);

    k_signorm<<<1, 128>>>(self_sigs);
    k_prepL<<<1, 256>>>(metric_L);
    k_gemm_mma<<<dim3(NB * MTOK   / 128, 2), 256, SMEM_TOT>>>(E, (float*)pEL);
    k_gemm_mma<<<dim3(NB * MPROTO / 128, 2), 256, SMEM_TOT>>>(K, (float*)pKL);
    k_epilogue<<<NB, 256>>>(E, K, danger, w_prev, fitness, crisis, proto_conf,
                            out_w, out_P);
}

// round 6
// speedup vs baseline: 1.4744x; 1.2087x over previous
#include <cuda_runtime.h>
#include <cuda_bf16.h>
#include <cstdint>
#include <math.h>

#define NB     16384
#define GB     9              // batches per block
#define ROWS   126            // 9 * 14 rows used (pad to 128)
#define DIM    256

// Pre-converted, pre-swizzled L operand: 4 k-chunks of [256 e-rows x 64 k] bf16
__device__ __nv_bfloat16 g_Lh[4 * 256 * 64];
__device__ __nv_bfloat16 g_Ll[4 * 256 * 64];

// ---------------- helpers ----------------
__device__ __forceinline__ uint32_t smem_u32(const void* p) {
    uint32_t a;
    asm("{ .reg .u64 t; cvta.to.shared.u64 t, %1; cvt.u32.u64 %0, t; }" : "=r"(a) : "l"(p));
    return a;
}
#define SWZ128(off) ((off) ^ (((off) >> 3) & 0x70))

#define LDSM4(r, addr)                                                          \
    asm volatile("ldmatrix.sync.aligned.m8n8.x4.shared.b16 {%0,%1,%2,%3}, [%4];"\
        : "=r"((r)[0]), "=r"((r)[1]), "=r"((r)[2]), "=r"((r)[3]) : "r"(addr))

#define MMA_BF16(d, a, b)                                                       \
    asm volatile("mma.sync.aligned.m16n8k16.row.col.f32.bf16.bf16.f32 "         \
        "{%0,%1,%2,%3}, {%4,%5,%6,%7}, {%8,%9}, {%0,%1,%2,%3};"                 \
        : "+f"((d)[0]), "+f"((d)[1]), "+f"((d)[2]), "+f"((d)[3])                \
        : "r"((a)[0]), "r"((a)[1]), "r"((a)[2]), "r"((a)[3]),                   \
          "r"((b)[0]), "r"((b)[1]))

// ---------------- prep: convert+pre-swizzle L into bf16 hi/lo ----------------
__global__ void k_prepL(const float* __restrict__ L)
{
    int r = blockIdx.x;            // e-row 0..255
    int k = threadIdx.x;           // k   0..255
    float x = L[r * 256 + k];
    __nv_bfloat16 h = __float2bfloat16(x);
    __nv_bfloat16 l = __float2bfloat16(x - __bfloat162float(h));
    int c  = k >> 6;
    int kc = k & 63;
    uint32_t off = SWZ128((uint32_t)(r * 128 + kc * 2));
    g_Lh[c * 16384 + (off >> 1)] = h;
    g_Ll[c * 16384 + (off >> 1)] = l;
}

// ---------------- fused kernel ----------------
// smem layout (bytes):
#define OFF_Y     0                  // 128 rows x 256 f32   = 131072
#define OFF_AH    131072             // 128 x 64 bf16        = 16384
#define OFF_AL    147456             // 16384
#define OFF_BH    163840             // 128 e-rows x 64 bf16 = 16384
#define OFF_BL    180224             // 16384
#define OFF_DANG  196608             // 9 x 256 f32          = 9216
#define OFF_SIG   205824             // 4 x 256 f32          = 4096
#define OFF_ROWST 209920             // 128 rows x 6 f32     = 3072
#define OFF_STATS 212992             // 9*62 f32 = 2232 -> 2240
#define SMEM_TOT  (OFF_STATS + 2240) // 215232 B

__global__ void __launch_bounds__(512, 1)
k_fused(const float* __restrict__ E, const float* __restrict__ Kp,
        const float* __restrict__ danger, const float* __restrict__ w_prev,
        const float* __restrict__ fitness, const float* __restrict__ crisis,
        const float* __restrict__ proto_conf, const float* __restrict__ self_sigs,
        float* __restrict__ out_w, float* __restrict__ out_P)
{
    extern __shared__ char sm[];
    const int tid  = threadIdx.x;
    const int w    = tid >> 5, lane = tid & 31;
    const int bg   = blockIdx.x;
    const uint32_t smb = smem_u32(sm);

    float* Y     = (float*)(sm + OFF_Y);
    float* sDang = (float*)(sm + OFF_DANG);
    float* sSig  = (float*)(sm + OFF_SIG);
    float* rowst = (float*)(sm + OFF_ROWST);
    float* sStat = (float*)(sm + OFF_STATS);

    // ---- load danger (9 batches) + raw sigs
    for (int i = tid; i < GB * 256; i += 512) {
        int b9 = i >> 8;
        int batch = bg * GB + b9; if (batch > NB - 1) batch = NB - 1;
        sDang[i] = danger[(size_t)batch * 256 + (i & 255)];
    }
    for (int i = tid; i < 1024; i += 512) sSig[i] = self_sigs[i];
    __syncthreads();
    if (w < 4) {                       // normalize sig row w in-place
        float a = 0.f;
        for (int d = lane; d < 256; d += 32) { float v = sSig[w * 256 + d]; a = fmaf(v, v, a); }
        #pragma unroll
        for (int o = 16; o; o >>= 1) a += __shfl_xor_sync(~0u, a, o);
        float inv = 1.0f / fmaxf(sqrtf(a), 1e-12f);
        for (int d = lane; d < 256; d += 32) sSig[w * 256 + d] *= inv;
    }
    __syncthreads();

    // ---- per-thread A-row mapping: thread t -> row t>>2, col quarter (t&3)*16
    const int arow = tid >> 2;
    const int q    = tid & 3;
    int rr = arow < ROWS ? arow : ROWS - 1;
    const int b9row = rr / 14;
    const int wr    = rr % 14;
    int batchR = bg * GB + b9row; if (batchR > NB - 1) batchR = NB - 1;
    const float* srcRow = (wr < 6) ? (E  + ((size_t)batchR * 6 + wr) * 256)
                                   : (Kp + ((size_t)batchR * 8 + (wr - 6)) * 256);
    const float* dang = sDang + b9row * 256;

    float sd = 0.f, s0 = 0.f, s1 = 0.f, s2 = 0.f, s3 = 0.f, snrm = 0.f;

    // ---- accumulators: [eh][mt][nt][4]
    float acc[2][2][4][4];
    #pragma unroll
    for (int eh = 0; eh < 2; eh++)
        #pragma unroll
        for (int mt = 0; mt < 2; mt++)
            #pragma unroll
            for (int nt = 0; nt < 4; nt++)
                #pragma unroll
                for (int j = 0; j < 4; j++) acc[eh][mt][nt][j] = 0.f;

    const int mbase = (w & 3) * 32;
    const int nbase = (w >> 2) * 32;
    const int arw   = mbase + (lane & 15);
    const int nrw   = nbase + (lane & 7) + ((lane >> 4) << 3);

    // ---- main loop over k-chunks
    #pragma unroll
    for (int c = 0; c < 4; c++) {
        // A convert (+ stats on fp32 values)
        {
            const float4* s4 = (const float4*)(srcRow + c * 64 + q * 16);
            char* ah = sm + OFF_AH;
            char* al = sm + OFF_AL;
            #pragma unroll
            for (int j = 0; j < 4; j++) {
                float4 v = s4[j];
                int kc  = q * 16 + j * 4;
                int col = c * 64 + kc;
                sd   = fmaf(v.x, dang[col],   fmaf(v.y, dang[col+1],   fmaf(v.z, dang[col+2],   fmaf(v.w, dang[col+3],   sd))));
                s0   = fmaf(v.x, sSig[col],   fmaf(v.y, sSig[col+1],   fmaf(v.z, sSig[col+2],   fmaf(v.w, sSig[col+3],   s0))));
                s1   = fmaf(v.x, sSig[256+col], fmaf(v.y, sSig[256+col+1], fmaf(v.z, sSig[256+col+2], fmaf(v.w, sSig[256+col+3], s1))));
                s2   = fmaf(v.x, sSig[512+col], fmaf(v.y, sSig[512+col+1], fmaf(v.z, sSig[512+col+2], fmaf(v.w, sSig[512+col+3], s2))));
                s3   = fmaf(v.x, sSig[768+col], fmaf(v.y, sSig[768+col+1], fmaf(v.z, sSig[768+col+2], fmaf(v.w, sSig[768+col+3], s3))));
                snrm = fmaf(v.x, v.x, fmaf(v.y, v.y, fmaf(v.z, v.z, fmaf(v.w, v.w, snrm))));

                __nv_bfloat16 h0 = __float2bfloat16(v.x);
                __nv_bfloat16 h1 = __float2bfloat16(v.y);
                __nv_bfloat16 h2 = __float2bfloat16(v.z);
                __nv_bfloat16 h3 = __float2bfloat16(v.w);
                __nv_bfloat16 l0 = __float2bfloat16(v.x - __bfloat162float(h0));
                __nv_bfloat16 l1 = __float2bfloat16(v.y - __bfloat162float(h1));
                __nv_bfloat16 l2 = __float2bfloat16(v.z - __bfloat162float(h2));
                __nv_bfloat16 l3 = __float2bfloat16(v.w - __bfloat162float(h3));
                uint32_t off = SWZ128((uint32_t)(arow * 128 + kc * 2));
                __nv_bfloat162 hA; hA.x = h0; hA.y = h1;
                __nv_bfloat162 hB; hB.x = h2; hB.y = h3;
                __nv_bfloat162 lA; lA.x = l0; lA.y = l1;
                __nv_bfloat162 lB; lB.x = l2; lB.y = l3;
                *(__nv_bfloat162*)(ah + off)     = hA;
                *(__nv_bfloat162*)(ah + off + 4) = hB;
                *(__nv_bfloat162*)(al + off)     = lA;
                *(__nv_bfloat162*)(al + off + 4) = lB;
            }
        }
        __syncthreads();

        #pragma unroll
        for (int eh = 0; eh < 2; eh++) {
            // B load: 16KB hi + 16KB lo (contiguous, swizzle-local copy)
            {
                const float4* gh = (const float4*)((const char*)g_Lh + c * 32768 + eh * 16384);
                const float4* gl = (const float4*)((const char*)g_Ll + c * 32768 + eh * 16384);
                float4* bh4 = (float4*)(sm + OFF_BH);
                float4* bl4 = (float4*)(sm + OFF_BL);
                #pragma unroll
                for (int i = 0; i < 2; i++) {
                    bh4[tid + i * 512] = gh[tid + i * 512];
                    bl4[tid + i * 512] = gl[tid + i * 512];
                }
            }
            __syncthreads();

            // mma over 4 k-steps
            {
                const uint32_t aH = smb + OFF_AH, aL = smb + OFF_AL;
                const uint32_t bH = smb + OFF_BH, bL = smb + OFF_BL;
                #pragma unroll
                for (int ks = 0; ks < 4; ks++) {
                    uint32_t ah[2][4], al[2][4], bh[2][4], bl[2][4];
                    const int akc = ks * 16 + (lane >> 4) * 8;
                    const int bkc = ks * 16 + ((lane >> 3) & 1) * 8;
                    #pragma unroll
                    for (int mt = 0; mt < 2; mt++) {
                        uint32_t off = SWZ128((uint32_t)((arw + mt * 16) * 128 + akc * 2));
                        LDSM4(ah[mt], aH + off);
                        LDSM4(al[mt], aL + off);
                    }
                    #pragma unroll
                    for (int g = 0; g < 2; g++) {
                        uint32_t off = SWZ128((uint32_t)((nrw + g * 16) * 128 + bkc * 2));
                        LDSM4(bh[g], bH + off);
                        LDSM4(bl[g], bL + off);
                    }
                    #pragma unroll
                    for (int mt = 0; mt < 2; mt++)
                        #pragma unroll
                        for (int nt = 0; nt < 4; nt++) {
                            uint32_t* Bh = &bh[nt >> 1][(nt & 1) * 2];
                            uint32_t* Bl = &bl[nt >> 1][(nt & 1) * 2];
                            MMA_BF16(acc[eh][mt][nt], ah[mt], Bh);
                            MMA_BF16(acc[eh][mt][nt], ah[mt], Bl);
                            MMA_BF16(acc[eh][mt][nt], al[mt], Bh);
                        }
                }
            }
            __syncthreads();
        }
    }

    // ---- reduce per-row stats across the 4 col-quarter threads (same warp, width 4)
    sd   += __shfl_xor_sync(~0u, sd,   1, 4);  sd   += __shfl_xor_sync(~0u, sd,   2, 4);
    s0   += __shfl_xor_sync(~0u, s0,   1, 4);  s0   += __shfl_xor_sync(~0u, s0,   2, 4);
    s1   += __shfl_xor_sync(~0u, s1,   1, 4);  s1   += __shfl_xor_sync(~0u, s1,   2, 4);
    s2   += __shfl_xor_sync(~0u, s2,   1, 4);  s2   += __shfl_xor_sync(~0u, s2,   2, 4);
    s3   += __shfl_xor_sync(~0u, s3,   1, 4);  s3   += __shfl_xor_sync(~0u, s3,   2, 4);
    snrm += __shfl_xor_sync(~0u, snrm, 1, 4);  snrm += __shfl_xor_sync(~0u, snrm, 2, 4);
    if (q == 0 && arow < ROWS) {
        float* rs = rowst + arow * 6;
        rs[0] = sd; rs[1] = s0; rs[2] = s1; rs[3] = s2; rs[4] = s3; rs[5] = snrm;
    }

    // ---- store Y tile to smem
    #pragma unroll
    for (int eh = 0; eh < 2; eh++)
        #pragma unroll
        for (int mt = 0; mt < 2; mt++) {
            const int row = mbase + mt * 16 + (lane >> 2);
            #pragma unroll
            for (int nt = 0; nt < 4; nt++) {
                const int col = eh * 128 + nbase + nt * 8 + (lane & 3) * 2;
                *(float2*)(Y + row * 256 + col)       = make_float2(acc[eh][mt][nt][0], acc[eh][mt][nt][1]);
                *(float2*)(Y + (row + 8) * 256 + col) = make_float2(acc[eh][mt][nt][2], acc[eh][mt][nt][3]);
            }
        }
    __syncthreads();

    // ---- phase 2a: 62 reductions per batch (48 cross + 6 E-norm + 8 K-norm)
    {
        const float4* Y4 = (const float4*)Y;
        for (int u = w; u < GB * 62; u += 16) {
            int bl_ = u / 62, t = u - bl_ * 62;
            int rA, rB;
            if (t < 48)      { rA = bl_ * 14 + (t >> 3); rB = bl_ * 14 + 6 + (t & 7); }
            else if (t < 54) { rA = bl_ * 14 + (t - 48);       rB = rA; }
            else             { rA = bl_ * 14 + 6 + (t - 54);   rB = rA; }
            float4 a0 = Y4[rA * 64 + lane * 2];
            float4 a1 = Y4[rA * 64 + lane * 2 + 1];
            float4 b0 = Y4[rB * 64 + lane * 2];
            float4 b1 = Y4[rB * 64 + lane * 2 + 1];
            float s = a0.x*b0.x + a0.y*b0.y + a0.z*b0.z + a0.w*b0.w
                    + a1.x*b1.x + a1.y*b1.y + a1.z*b1.z + a1.w*b1.w;
            #pragma unroll
            for (int o = 16; o; o >>= 1) s += __shfl_xor_sync(~0u, s, o);
            if (lane == 0) sStat[u] = s;
        }
    }
    __syncthreads();

    // ---- phase 2b: C build + Sinkhorn + replicator (warp b handles batch b)
    if (w < GB) {
        const int batch = bg * GB + w;
        if (batch < NB) {
            const float* st = sStat + w * 62;
            const int n = lane & 7;
            const float nK = st[54 + n];

            // K-row stats for proto n
            const float* rsk = rowst + (w * 14 + 6 + n) * 6;
            float kn  = fmaxf(sqrtf(rsk[5]), 1e-12f);
            float pss = fmaxf(fmaxf(rsk[1], rsk[2]), fmaxf(rsk[3], rsk[4])) / kn;

            const float pc = proto_conf[(size_t)batch * 8 + n];

            const float INV_EPS = 1.0f / (0.05f + 1e-8f);
            const float LOG_U = logf(1.0f / 6.0f + 1e-8f);
            const float LOG_V = logf(0.125f     + 1e-8f);
            float lk[6], la[6], lb = 0.0f;
            #pragma unroll
            for (int m = 0; m < 6; m++) {
                const float* rse = rowst + (w * 14 + m) * 6;
                float en    = fmaxf(sqrtf(rse[5]), 1e-12f);
                float worst = fmaxf(fmaxf(rse[1], rse[2]), fmaxf(rse[3], rse[4])) / en;
                float tp    = fmaxf(worst - 0.1f, 0.0f);
                float msq   = st[48 + m] + nK - 2.0f * st[m * 8 + n];
                float dist  = sqrtf(fmaxf(msq, 1e-8f));
                float C     = dist - 0.5f * rse[0] + 2.0f * tp + 0.3f * pc;
                lk[m] = -C * INV_EPS;
                la[m] = 0.f;
            }

            for (int it = 0; it < 10; it++) {
                float t2[6];
                #pragma unroll
                for (int m = 0; m < 6; m++) {
                    float t = lk[m] + lb;
                    float r = t;
                    r = fmaxf(r, __shfl_xor_sync(~0u, r, 1, 8));
                    r = fmaxf(r, __shfl_xor_sync(~0u, r, 2, 8));
                    r = fmaxf(r, __shfl_xor_sync(~0u, r, 4, 8));
                    float s = expf(t - r);
                    s += __shfl_xor_sync(~0u, s, 1, 8);
                    s += __shfl_xor_sync(~0u, s, 2, 8);
                    s += __shfl_xor_sync(~0u, s, 4, 8);
                    la[m] = LOG_U - (r + logf(s));
                    t2[m] = lk[m] + la[m];
                }
                float cm = t2[0];
                #pragma unroll
                for (int m = 1; m < 6; m++) cm = fmaxf(cm, t2[m]);
                float cs = 0.f;
                #pragma unroll
                for (int m = 0; m < 6; m++) cs += expf(t2[m] - cm);
                lb = LOG_V - (cm + logf(cs));
            }

            float pm = 0.0f;
            #pragma unroll
            for (int m = 0; m < 6; m++) {
                float p = expf(la[m] + lk[m] + lb);
                p = fminf(fmaxf(p, 0.0f), 1.0f);
                if (lane < 8) out_P[(size_t)batch * 48 + m * 8 + n] = p;
                pm += p;
            }

            float wp  = w_prev [(size_t)batch * 8 + n];
            float fit = fitness[(size_t)batch * 8 + n];
            float bl = wp * fit;
            bl += __shfl_xor_sync(~0u, bl, 1, 8);
            bl += __shfl_xor_sync(~0u, bl, 2, 8);
            bl += __shfl_xor_sync(~0u, bl, 4, 8);
            float eta = 0.05f + 0.1f * crisis[batch];
            float lt = logf(wp + 1e-8f) + eta * (fit - bl) - 0.5f * pss;
            float mx = lt;
            mx = fmaxf(mx, __shfl_xor_sync(~0u, mx, 1, 8));
            mx = fmaxf(mx, __shfl_xor_sync(~0u, mx, 2, 8));
            mx = fmaxf(mx, __shfl_xor_sync(~0u, mx, 4, 8));
            float ex = expf(lt - mx);
            float ss = ex;
            ss += __shfl_xor_sync(~0u, ss, 1, 8);
            ss += __shfl_xor_sync(~0u, ss, 2, 8);
            ss += __shfl_xor_sync(~0u, ss, 4, 8);
            float tilde = ex / ss;
            float wv = 0.7f * tilde + 0.3f * pm;
            float ws = wv;
            ws += __shfl_xor_sync(~0u, ws, 1, 8);
            ws += __shfl_xor_sync(~0u, ws, 2, 8);
            ws += __shfl_xor_sync(~0u, ws, 4, 8);
            wv = wv / (ws + 1e-8f);
            wv = fminf(fmaxf(wv, 1e-6f), 1.0f);
            if (lane < 8) out_w[(size_t)batch * 8 + n] = wv;
        }
    }
}

// ---------------- launch ----------------
extern "C" void kernel_launch(void* const* d_in, const int* in_sizes, int n_in,
                              void* d_out, int out_size)
{
    const float* E          = (const float*)d_in[0];
    const float* K          = (const float*)d_in[1];
    const float* danger     = (const float*)d_in[2];
    const float* w_prev     = (const float*)d_in[3];
    const float* fitness    = (const float*)d_in[4];
    const float* crisis     = (const float*)d_in[5];
    const float* proto_conf = (const float*)d_in[6];
    const float* metric_L   = (const float*)d_in[7];
    const float* self_sigs  = (const float*)d_in[8];

    float* out   = (float*)d_out;
    float* out_w = out;                       // [B, 8]
    float* out_P = out + (size_t)NB * 8;      // [B, 6, 8]

    cudaFuncSetAttribute(k_fused, cudaFuncAttributeMaxDynamicSharedMemorySize,
                         SMEM_TOT);

    const int grid = (NB + GB - 1) / GB;      // 1821

    k_prepL<<<256, 256>>>(metric_L);
    k_fused<<<grid, 512, SMEM_TOT>>>(E, K, danger, w_prev, fitness, crisis,
                                     proto_conf, self_sigs, out_w, out_P);
}